// round 6
// baseline (speedup 1.0000x reference)
#include <cuda_runtime.h>
#include <math_constants.h>

// Outputs packed float32, reference return order:
//   [0,    N)   t_hit
//   [N,   2N)   sphere_idx (as float, -1 for miss)
//   [2N,  5N)   hit_points  (N,3)
//   [5N,  8N)   hit_normals (N,3)
//
// Decision arithmetic bit-replicates the reference fp32 op sequence in the
// half-b domain (power-of-two / sign scalings commute exactly with rn
// rounding, sqrt, div). Inner loop: 2 spheres/lane via packed f32x2 ops
// (12 packed ops/pair). Sphere data is block-invariant -> lives in
// __constant__ memory so uniform-index loads go through the LDCU/uniform
// path (no LDS, no smem latency, data in uniform registers).

#define MAX_SPH  256
#define MAX_PAIR (MAX_SPH / 2)
#define BLOCK    256

typedef unsigned long long u64;

__device__ __forceinline__ u64 mul2(u64 a, u64 b) {
    u64 d; asm("mul.rn.f32x2 %0, %1, %2;" : "=l"(d) : "l"(a), "l"(b)); return d;
}
__device__ __forceinline__ u64 add2(u64 a, u64 b) {
    u64 d; asm("add.rn.f32x2 %0, %1, %2;" : "=l"(d) : "l"(a), "l"(b)); return d;
}
__device__ __forceinline__ u64 fma2(u64 a, u64 b, u64 c) {
    u64 d; asm("fma.rn.f32x2 %0, %1, %2, %3;" : "=l"(d) : "l"(a), "l"(b), "l"(c)); return d;
}
__device__ __forceinline__ u64 pkf(float lo, float hi) {
    return (u64)__float_as_uint(lo) | ((u64)__float_as_uint(hi) << 32);
}
__device__ __forceinline__ float lo_f(u64 v) { return __int_as_float((int)(unsigned)v); }
__device__ __forceinline__ float hi_f(u64 v) { return __int_as_float((int)(v >> 32)); }

// Staging (written by prep kernel) and constant tables (memcpy'd from staging).
__device__ ulonglong2 g_stage_xy[MAX_PAIR];
__device__ ulonglong2 g_stage_zw[MAX_PAIR];
__device__ float4     g_stage_ctr[MAX_SPH];

__constant__ ulonglong2 c_XY[MAX_PAIR];   // {pack(x0,x1), pack(y0,y1)}
__constant__ ulonglong2 c_ZW[MAX_PAIR];   // {pack(z0,z1), pack(w0,w1)}, w=|c|^2-r^2
__constant__ float4     c_ctr[MAX_SPH];   // (cx,cy,cz,w) for gather + odd tail

__global__ void prep_kernel(const float* __restrict__ sc,
                            const float* __restrict__ sr,
                            int n_sph)
{
    __shared__ float4 s_tmp[MAX_SPH];
    const int j = threadIdx.x;
    if (j < n_sph) {
        float cx = sc[3 * j + 0];
        float cy = sc[3 * j + 1];
        float cz = sc[3 * j + 2];
        float r  = sr[j];
        float s2 = __fadd_rn(__fadd_rn(__fmul_rn(cx, cx), __fmul_rn(cy, cy)),
                             __fmul_rn(cz, cz));
        float w  = __fsub_rn(s2, __fmul_rn(r, r));
        float4 v = make_float4(cx, cy, cz, w);
        s_tmp[j] = v;
        g_stage_ctr[j] = v;
    }
    __syncthreads();
    const int n_pair = n_sph >> 1;
    if (j < n_pair) {
        float4 p0 = s_tmp[2 * j], p1 = s_tmp[2 * j + 1];
        g_stage_xy[j] = make_ulonglong2(pkf(p0.x, p1.x), pkf(p0.y, p1.y));
        g_stage_zw[j] = make_ulonglong2(pkf(p0.z, p1.z), pkf(p0.w, p1.w));
    }
}

__global__ __launch_bounds__(BLOCK)
void raysphere_kernel(const float* __restrict__ ro,
                      const float* __restrict__ rd,
                      float* __restrict__ out,
                      int n_rays, int n_sph)
{
    const int i = blockIdx.x * BLOCK + threadIdx.x;
    if (i >= n_rays) return;

    const float ox = ro[3 * i + 0];
    const float oy = ro[3 * i + 1];
    const float oz = ro[3 * i + 2];
    const float dx = rd[3 * i + 0];
    const float dy = rd[3 * i + 1];
    const float dz = rd[3 * i + 2];

    // jnp.sum(v*v): rounded squares, left-to-right add (reference order)
    const float a   = __fadd_rn(__fadd_rn(__fmul_rn(dx, dx), __fmul_rn(dy, dy)),
                                __fmul_rn(dz, dz));
    const float ddo = __fadd_rn(__fadd_rn(__fmul_rn(dx, ox), __fmul_rn(dy, oy)),
                                __fmul_rn(dz, oz));
    const float on2 = __fadd_rn(__fadd_rn(__fmul_rn(ox, ox), __fmul_rn(oy, oy)),
                                __fmul_rn(oz, oz));

    // Packed broadcast ray constants.
    // d-chain negated (exact sign flip) -> -ddc.
    // o-chain scaled by -2 (exact power-of-two*sign scale, commutes with rn
    // at every fma step) -> -2*odc bitwise, eliminating a separate doubling.
    const float n2ox = __fmul_rn(-2.0f, ox);
    const float n2oy = __fmul_rn(-2.0f, oy);
    const float n2oz = __fmul_rn(-2.0f, oz);
    const u64 pndx  = pkf(-dx, -dx), pndy  = pkf(-dy, -dy), pndz  = pkf(-dz, -dz);
    const u64 pn2ox = pkf(n2ox, n2ox), pn2oy = pkf(n2oy, n2oy), pn2oz = pkf(n2oz, n2oz);
    const u64 pddo = pkf(ddo, ddo);
    const u64 pon2 = pkf(on2, on2);
    const u64 pna  = pkf(-a, -a);

    float best_m = CUDART_INF_F;   // half-b numerator reject bound
    float best_t = CUDART_INF_F;   // reference-exact t
    int   best_j = 0;

    const int n_pair = n_sph >> 1;

    #pragma unroll 8
    for (int k = 0; k < n_pair; k++) {
        const ulonglong2 A = c_XY[k];     // A.x={x0,x1}  A.y={y0,y1}
        const ulonglong2 B = c_ZW[k];     // B.x={z0,z1}  B.y={w0,w1}

        // -ddc, -2*odc : exact transforms of the reference fma chains (k=0->2)
        const u64 nddc  = fma2(pndz,  B.x, fma2(pndy,  A.y, mul2(pndx,  A.x)));
        const u64 n2odc = fma2(pn2oz, B.x, fma2(pn2oy, A.y, mul2(pn2ox, A.x)));

        const u64 x2 = add2(pddo, nddc);              //  ddo - ddc  (= b/2)
        const u64 c2 = add2(add2(pon2, n2odc), B.y);  //  (on2-2odc)+cconst
        const u64 q2 = add2(mul2(x2, x2), mul2(pna, c2));   // disc/4 per lane

        // "any lane >= 0" == NOT(both sign bits set). (-0.0f cannot occur:
        // rn cancellation yields +0, so sign-bit <=> q < 0.)
        const int qlo_i = (int)(unsigned)q2;
        const int qhi_i = (int)(q2 >> 32);
        if ((qlo_i & qhi_i) >= 0) {                  // rare tail
            const float qlo = __int_as_float(qlo_i);
            const float qhi = __int_as_float(qhi_i);
            if (qlo >= 0.0f) {
                const float x  = lo_f(x2);
                const float sq = __fsqrt_rn(qlo);    // = sqrt_disc/2 exactly
                const float m1 = __fsub_rn(-x, sq);
                const float m0 = __fadd_rn(-x, sq);
                const float m  = (m1 > 0.0f) ? m1 : m0;
                if (m > 0.0f && m < best_m) {
                    best_m = m;
                    const float t = __fdiv_rn(m, a); // == num/(2a) exactly
                    if (t < best_t) { best_t = t; best_j = 2 * k; }
                }
            }
            if (qhi >= 0.0f) {
                const float x  = hi_f(x2);
                const float sq = __fsqrt_rn(qhi);
                const float m1 = __fsub_rn(-x, sq);
                const float m0 = __fadd_rn(-x, sq);
                const float m  = (m1 > 0.0f) ? m1 : m0;
                if (m > 0.0f && m < best_m) {
                    best_m = m;
                    const float t = __fdiv_rn(m, a);
                    if (t < best_t) { best_t = t; best_j = 2 * k + 1; }
                }
            }
        }
    }

    // Scalar remainder if n_sph is odd (not hit for 256)
    for (int j = 2 * n_pair; j < n_sph; j++) {
        const float4 s = c_ctr[j];
        const float ddc = __fmaf_rn(dz, s.z, __fmaf_rn(dy, s.y, __fmul_rn(dx, s.x)));
        const float odc = __fmaf_rn(oz, s.z, __fmaf_rn(oy, s.y, __fmul_rn(ox, s.x)));
        const float x   = __fsub_rn(ddo, ddc);
        const float c   = __fadd_rn(__fsub_rn(on2, __fmul_rn(2.0f, odc)), s.w);
        const float q   = __fsub_rn(__fmul_rn(x, x), __fmul_rn(a, c));
        if (q >= 0.0f) {
            const float sq = __fsqrt_rn(q);
            const float m1 = __fsub_rn(-x, sq);
            const float m0 = __fadd_rn(-x, sq);
            const float m  = (m1 > 0.0f) ? m1 : m0;
            if (m > 0.0f && m < best_m) {
                best_m = m;
                const float t = __fdiv_rn(m, a);
                if (t < best_t) { best_t = t; best_j = j; }
            }
        }
    }

    const float t_hit = best_t;
    const bool  any   = isfinite(t_hit);

    const long long N = n_rays;
    out[i]     = t_hit;
    out[N + i] = any ? (float)best_j : -1.0f;

    // hit_points = o + t*d (mul then add — matches reference)
    const float hx = __fadd_rn(ox, __fmul_rn(t_hit, dx));
    const float hy = __fadd_rn(oy, __fmul_rn(t_hit, dy));
    const float hz = __fadd_rn(oz, __fmul_rn(t_hit, dz));
    out[2 * N + 3 * i + 0] = hx;
    out[2 * N + 3 * i + 1] = hy;
    out[2 * N + 3 * i + 2] = hz;

    const float4 cb = c_ctr[any ? best_j : 0];   // divergent LDC, once per ray
    const float nx = __fsub_rn(hx, cb.x);
    const float ny = __fsub_rn(hy, cb.y);
    const float nz = __fsub_rn(hz, cb.z);
    const float nn = __fadd_rn(__fadd_rn(__fmul_rn(nx, nx), __fmul_rn(ny, ny)),
                               __fmul_rn(nz, nz));
    const float len = __fsqrt_rn(nn);
    out[5 * N + 3 * i + 0] = any ? __fdiv_rn(nx, len) : 0.0f;
    out[5 * N + 3 * i + 1] = any ? __fdiv_rn(ny, len) : 0.0f;
    out[5 * N + 3 * i + 2] = any ? __fdiv_rn(nz, len) : 0.0f;
}

extern "C" void kernel_launch(void* const* d_in, const int* in_sizes, int n_in,
                              void* d_out, int out_size)
{
    const float* ro = (const float*)d_in[0];   // (N,3)
    const float* rd = (const float*)d_in[1];   // (N,3)
    const float* sc = (const float*)d_in[2];   // (M,3)
    const float* sr = (const float*)d_in[3];   // (M,)

    const int n_rays = in_sizes[0] / 3;
    const int n_sph  = in_sizes[3];

    float* out = (float*)d_out;

    // 1) Precompute packed sphere tables into __device__ staging.
    prep_kernel<<<1, BLOCK>>>(sc, sr, n_sph);

    // 2) Stage -> __constant__ (device-to-device, graph-capturable memcpys).
    void* src_xy  = nullptr;
    void* src_zw  = nullptr;
    void* src_ctr = nullptr;
    cudaGetSymbolAddress(&src_xy,  g_stage_xy);
    cudaGetSymbolAddress(&src_zw,  g_stage_zw);
    cudaGetSymbolAddress(&src_ctr, g_stage_ctr);
    cudaMemcpyToSymbolAsync(c_XY,  src_xy,  sizeof(ulonglong2) * MAX_PAIR, 0,
                            cudaMemcpyDeviceToDevice, 0);
    cudaMemcpyToSymbolAsync(c_ZW,  src_zw,  sizeof(ulonglong2) * MAX_PAIR, 0,
                            cudaMemcpyDeviceToDevice, 0);
    cudaMemcpyToSymbolAsync(c_ctr, src_ctr, sizeof(float4) * MAX_SPH, 0,
                            cudaMemcpyDeviceToDevice, 0);

    // 3) Main kernel reads spheres through the constant/uniform path.
    const int grid = (n_rays + BLOCK - 1) / BLOCK;
    raysphere_kernel<<<grid, BLOCK>>>(ro, rd, out, n_rays, n_sph);
}

// round 7
// speedup vs baseline: 1.3864x; 1.3864x over previous
#include <cuda_runtime.h>
#include <math_constants.h>

// Outputs packed float32, reference return order:
//   [0,    N)   t_hit
//   [N,   2N)   sphere_idx (as float, -1 for miss)
//   [2N,  5N)   hit_points  (N,3)
//   [5N,  8N)   hit_normals (N,3)
//
// Decision arithmetic bit-replicates the reference fp32 op sequence in the
// half-b domain (power-of-two / sign scalings commute exactly with rn
// rounding, sqrt, div). Hot loop: 2 spheres/lane via packed f32x2 ops
// (12 packed ops per ray per pair) and 2 RAYS per thread sharing each
// pair's LDS.128 loads and one combined branch envelope.

#define MAX_SPH  256
#define MAX_PAIR (MAX_SPH / 2)
#define BLOCK    256

typedef unsigned long long u64;

__device__ __forceinline__ u64 mul2(u64 a, u64 b) {
    u64 d; asm("mul.rn.f32x2 %0, %1, %2;" : "=l"(d) : "l"(a), "l"(b)); return d;
}
__device__ __forceinline__ u64 add2(u64 a, u64 b) {
    u64 d; asm("add.rn.f32x2 %0, %1, %2;" : "=l"(d) : "l"(a), "l"(b)); return d;
}
__device__ __forceinline__ u64 fma2(u64 a, u64 b, u64 c) {
    u64 d; asm("fma.rn.f32x2 %0, %1, %2, %3;" : "=l"(d) : "l"(a), "l"(b), "l"(c)); return d;
}
__device__ __forceinline__ u64 pkf(float lo, float hi) {
    return (u64)__float_as_uint(lo) | ((u64)__float_as_uint(hi) << 32);
}
__device__ __forceinline__ float lo_f(u64 v) { return __int_as_float((int)(unsigned)v); }
__device__ __forceinline__ float hi_f(u64 v) { return __int_as_float((int)(v >> 32)); }

struct RayState {
    // packed broadcast constants
    u64 pndx, pndy, pndz;       // {-d, -d}
    u64 pn2ox, pn2oy, pn2oz;    // {-2o, -2o}
    u64 pddo, pon2, pna;
    // scalars
    float ox, oy, oz, dx, dy, dz, a, ddo, on2;
    // running best
    float best_m, best_t;
    int   best_j;
};

__device__ __forceinline__ void ray_init(RayState& R,
                                         const float* __restrict__ ro,
                                         const float* __restrict__ rd, int i)
{
    const float ox = ro[3 * i + 0], oy = ro[3 * i + 1], oz = ro[3 * i + 2];
    const float dx = rd[3 * i + 0], dy = rd[3 * i + 1], dz = rd[3 * i + 2];
    // jnp.sum(v*v): rounded squares, left-to-right add (reference order)
    const float a   = __fadd_rn(__fadd_rn(__fmul_rn(dx, dx), __fmul_rn(dy, dy)),
                                __fmul_rn(dz, dz));
    const float ddo = __fadd_rn(__fadd_rn(__fmul_rn(dx, ox), __fmul_rn(dy, oy)),
                                __fmul_rn(dz, oz));
    const float on2 = __fadd_rn(__fadd_rn(__fmul_rn(ox, ox), __fmul_rn(oy, oy)),
                                __fmul_rn(oz, oz));
    const float n2ox = __fmul_rn(-2.0f, ox);
    const float n2oy = __fmul_rn(-2.0f, oy);
    const float n2oz = __fmul_rn(-2.0f, oz);
    R.pndx = pkf(-dx, -dx); R.pndy = pkf(-dy, -dy); R.pndz = pkf(-dz, -dz);
    R.pn2ox = pkf(n2ox, n2ox); R.pn2oy = pkf(n2oy, n2oy); R.pn2oz = pkf(n2oz, n2oz);
    R.pddo = pkf(ddo, ddo); R.pon2 = pkf(on2, on2); R.pna = pkf(-a, -a);
    R.ox = ox; R.oy = oy; R.oz = oz; R.dx = dx; R.dy = dy; R.dz = dz;
    R.a = a; R.ddo = ddo; R.on2 = on2;
    R.best_m = CUDART_INF_F; R.best_t = CUDART_INF_F; R.best_j = 0;
}

// Rare-path: resolve one packed pair's candidates for one ray (exact ref math)
__device__ __forceinline__ void resolve_pair(RayState& R, u64 q2, u64 x2, int k)
{
    const float qlo = lo_f(q2), qhi = hi_f(q2);
    if (qlo >= 0.0f) {
        const float x  = lo_f(x2);
        const float sq = __fsqrt_rn(qlo);            // = sqrt_disc/2 exactly
        const float m1 = __fsub_rn(-x, sq);
        const float m0 = __fadd_rn(-x, sq);
        const float m  = (m1 > 0.0f) ? m1 : m0;
        if (m > 0.0f && m < R.best_m) {
            R.best_m = m;
            const float t = __fdiv_rn(m, R.a);       // == num/(2a) exactly
            if (t < R.best_t) { R.best_t = t; R.best_j = 2 * k; }
        }
    }
    if (qhi >= 0.0f) {
        const float x  = hi_f(x2);
        const float sq = __fsqrt_rn(qhi);
        const float m1 = __fsub_rn(-x, sq);
        const float m0 = __fadd_rn(-x, sq);
        const float m  = (m1 > 0.0f) ? m1 : m0;
        if (m > 0.0f && m < R.best_m) {
            R.best_m = m;
            const float t = __fdiv_rn(m, R.a);
            if (t < R.best_t) { R.best_t = t; R.best_j = 2 * k + 1; }
        }
    }
}

__device__ __forceinline__ void ray_write(const RayState& R,
                                          const float4* __restrict__ s_ctr,
                                          float* __restrict__ out,
                                          long long N, int i)
{
    const float t_hit = R.best_t;
    const bool  any   = isfinite(t_hit);
    out[i]     = t_hit;
    out[N + i] = any ? (float)R.best_j : -1.0f;
    // hit_points = o + t*d (mul then add — matches reference)
    const float hx = __fadd_rn(R.ox, __fmul_rn(t_hit, R.dx));
    const float hy = __fadd_rn(R.oy, __fmul_rn(t_hit, R.dy));
    const float hz = __fadd_rn(R.oz, __fmul_rn(t_hit, R.dz));
    out[2 * N + 3 * i + 0] = hx;
    out[2 * N + 3 * i + 1] = hy;
    out[2 * N + 3 * i + 2] = hz;
    const float4 cb = s_ctr[any ? R.best_j : 0];
    const float nx = __fsub_rn(hx, cb.x);
    const float ny = __fsub_rn(hy, cb.y);
    const float nz = __fsub_rn(hz, cb.z);
    const float nn = __fadd_rn(__fadd_rn(__fmul_rn(nx, nx), __fmul_rn(ny, ny)),
                               __fmul_rn(nz, nz));
    const float len = __fsqrt_rn(nn);
    out[5 * N + 3 * i + 0] = any ? __fdiv_rn(nx, len) : 0.0f;
    out[5 * N + 3 * i + 1] = any ? __fdiv_rn(ny, len) : 0.0f;
    out[5 * N + 3 * i + 2] = any ? __fdiv_rn(nz, len) : 0.0f;
}

__global__ __launch_bounds__(BLOCK)
void raysphere_kernel(const float* __restrict__ ro,
                      const float* __restrict__ rd,
                      const float* __restrict__ sc,
                      const float* __restrict__ sr,
                      float* __restrict__ out,
                      int n_rays, int n_sph)
{
    // Pre-packed pair data: sXY[k] = {pack(x0,x1), pack(y0,y1)},
    //                       sZW[k] = {pack(z0,z1), pack(w0,w1)}, w = |c|^2-r^2
    __shared__ ulonglong2 sXY[MAX_PAIR];
    __shared__ ulonglong2 sZW[MAX_PAIR];
    __shared__ float4     s_ctr[MAX_SPH];

    const int tid    = threadIdx.x;
    const int n_pair = n_sph >> 1;

    for (int j = tid; j < n_sph; j += BLOCK) {
        float cx = sc[3 * j + 0];
        float cy = sc[3 * j + 1];
        float cz = sc[3 * j + 2];
        float r  = sr[j];
        float s2 = __fadd_rn(__fadd_rn(__fmul_rn(cx, cx), __fmul_rn(cy, cy)),
                             __fmul_rn(cz, cz));
        float w  = __fsub_rn(s2, __fmul_rn(r, r));
        s_ctr[j] = make_float4(cx, cy, cz, w);
    }
    __syncthreads();
    for (int k = tid; k < n_pair; k += BLOCK) {
        float4 p0 = s_ctr[2 * k], p1 = s_ctr[2 * k + 1];
        sXY[k] = make_ulonglong2(pkf(p0.x, p1.x), pkf(p0.y, p1.y));
        sZW[k] = make_ulonglong2(pkf(p0.z, p1.z), pkf(p0.w, p1.w));
    }
    __syncthreads();

    // Two rays per thread: i0 and i0 + half (fully coalesced both halves)
    const int half = (n_rays + 1) >> 1;
    const int i0 = blockIdx.x * BLOCK + tid;
    if (i0 >= half) return;
    const int  i1 = i0 + half;
    const bool v1 = (i1 < n_rays);
    const int  i1c = v1 ? i1 : i0;

    RayState R0, R1;
    ray_init(R0, ro, rd, i0);
    ray_init(R1, ro, rd, i1c);

    #pragma unroll 4
    for (int k = 0; k < n_pair; k++) {
        const ulonglong2 A = sXY[k];      // {x0,x1},{y0,y1}
        const ulonglong2 B = sZW[k];      // {z0,z1},{w0,w1}

        // Ray 0
        const u64 nddc0  = fma2(R0.pndz,  B.x, fma2(R0.pndy,  A.y, mul2(R0.pndx,  A.x)));
        const u64 n2odc0 = fma2(R0.pn2oz, B.x, fma2(R0.pn2oy, A.y, mul2(R0.pn2ox, A.x)));
        const u64 x20 = add2(R0.pddo, nddc0);
        const u64 c20 = add2(add2(R0.pon2, n2odc0), B.y);
        const u64 q20 = add2(mul2(x20, x20), mul2(R0.pna, c20));

        // Ray 1
        const u64 nddc1  = fma2(R1.pndz,  B.x, fma2(R1.pndy,  A.y, mul2(R1.pndx,  A.x)));
        const u64 n2odc1 = fma2(R1.pn2oz, B.x, fma2(R1.pn2oy, A.y, mul2(R1.pn2ox, A.x)));
        const u64 x21 = add2(R1.pddo, nddc1);
        const u64 c21 = add2(add2(R1.pon2, n2odc1), B.y);
        const u64 q21 = add2(mul2(x21, x21), mul2(R1.pna, c21));

        // Combined test: any of the 4 q lanes >= 0? (no -0.0f possible:
        // rn cancellation yields +0, so sign-bit <=> q < 0)
        const u64 qa = q20 & q21;
        const int sb = (int)((unsigned)qa & (unsigned)(qa >> 32));
        if (sb >= 0) {                                // rare tail
            resolve_pair(R0, q20, x20, k);
            resolve_pair(R1, q21, x21, k);
        }
    }

    // Scalar remainder if n_sph is odd (not hit for 256)
    for (int j = 2 * n_pair; j < n_sph; j++) {
        const float4 s = s_ctr[j];
        #pragma unroll
        for (int r = 0; r < 2; r++) {
            RayState& R = r ? R1 : R0;
            const float ddc = __fmaf_rn(R.dz, s.z, __fmaf_rn(R.dy, s.y, __fmul_rn(R.dx, s.x)));
            const float odc = __fmaf_rn(R.oz, s.z, __fmaf_rn(R.oy, s.y, __fmul_rn(R.ox, s.x)));
            const float x   = __fsub_rn(R.ddo, ddc);
            const float c   = __fadd_rn(__fsub_rn(R.on2, __fmul_rn(2.0f, odc)), s.w);
            const float q   = __fsub_rn(__fmul_rn(x, x), __fmul_rn(R.a, c));
            if (q >= 0.0f) {
                const float sq = __fsqrt_rn(q);
                const float m1 = __fsub_rn(-x, sq);
                const float m0 = __fadd_rn(-x, sq);
                const float m  = (m1 > 0.0f) ? m1 : m0;
                if (m > 0.0f && m < R.best_m) {
                    R.best_m = m;
                    const float t = __fdiv_rn(m, R.a);
                    if (t < R.best_t) { R.best_t = t; R.best_j = j; }
                }
            }
        }
    }

    const long long N = n_rays;
    ray_write(R0, s_ctr, out, N, i0);
    if (v1) ray_write(R1, s_ctr, out, N, i1);
}

extern "C" void kernel_launch(void* const* d_in, const int* in_sizes, int n_in,
                              void* d_out, int out_size)
{
    const float* ro = (const float*)d_in[0];   // (N,3)
    const float* rd = (const float*)d_in[1];   // (N,3)
    const float* sc = (const float*)d_in[2];   // (M,3)
    const float* sr = (const float*)d_in[3];   // (M,)

    const int n_rays = in_sizes[0] / 3;
    const int n_sph  = in_sizes[3];

    float* out = (float*)d_out;

    const int half = (n_rays + 1) / 2;
    const int grid = (half + BLOCK - 1) / BLOCK;
    raysphere_kernel<<<grid, BLOCK>>>(ro, rd, sc, sr, out, n_rays, n_sph);
}

// round 8
// speedup vs baseline: 1.6637x; 1.2000x over previous
#include <cuda_runtime.h>
#include <math_constants.h>

// Outputs packed float32, reference return order:
//   [0,    N)   t_hit
//   [N,   2N)   sphere_idx (as float, -1 for miss)
//   [2N,  5N)   hit_points  (N,3)
//   [5N,  8N)   hit_normals (N,3)
//
// Decision arithmetic bit-replicates the reference fp32 op sequence in the
// half-b domain (power-of-two / sign scalings commute exactly with rn
// rounding, sqrt, div).
// Main loop is BRANCH-FREE: 2 spheres/lane via packed f32x2 (12 packed ops
// per pair) + 3 ALU ops that shift a hit bit into a mask. A short resolution
// pass then redoes exact scalar math only for flagged pairs, scanning masks
// MSB-first so sphere indices are visited ascending (reference tie-break).

#define MAX_SPH  256
#define MAX_PAIR (MAX_SPH / 2)
#define BLOCK    256

typedef unsigned long long u64;
typedef unsigned int       u32;

__device__ __forceinline__ u64 mul2(u64 a, u64 b) {
    u64 d; asm("mul.rn.f32x2 %0, %1, %2;" : "=l"(d) : "l"(a), "l"(b)); return d;
}
__device__ __forceinline__ u64 add2(u64 a, u64 b) {
    u64 d; asm("add.rn.f32x2 %0, %1, %2;" : "=l"(d) : "l"(a), "l"(b)); return d;
}
__device__ __forceinline__ u64 fma2(u64 a, u64 b, u64 c) {
    u64 d; asm("fma.rn.f32x2 %0, %1, %2, %3;" : "=l"(d) : "l"(a), "l"(b), "l"(c)); return d;
}
__device__ __forceinline__ u64 pkf(float lo, float hi) {
    return (u64)__float_as_uint(lo) | ((u64)__float_as_uint(hi) << 32);
}

__global__ __launch_bounds__(BLOCK)
void raysphere_kernel(const float* __restrict__ ro,
                      const float* __restrict__ rd,
                      const float* __restrict__ sc,
                      const float* __restrict__ sr,
                      float* __restrict__ out,
                      int n_rays, int n_sph)
{
    // Pre-packed pair data: sXY[k] = {pack(x0,x1), pack(y0,y1)},
    //                       sZW[k] = {pack(z0,z1), pack(w0,w1)}, w = |c|^2-r^2
    __shared__ ulonglong2 sXY[MAX_PAIR];
    __shared__ ulonglong2 sZW[MAX_PAIR];
    __shared__ float4     s_ctr[MAX_SPH];

    const int tid    = threadIdx.x;
    const int n_pair = n_sph >> 1;

    for (int j = tid; j < n_sph; j += BLOCK) {
        float cx = sc[3 * j + 0];
        float cy = sc[3 * j + 1];
        float cz = sc[3 * j + 2];
        float r  = sr[j];
        float s2 = __fadd_rn(__fadd_rn(__fmul_rn(cx, cx), __fmul_rn(cy, cy)),
                             __fmul_rn(cz, cz));
        float w  = __fsub_rn(s2, __fmul_rn(r, r));
        s_ctr[j] = make_float4(cx, cy, cz, w);
    }
    __syncthreads();
    for (int k = tid; k < n_pair; k += BLOCK) {
        float4 p0 = s_ctr[2 * k], p1 = s_ctr[2 * k + 1];
        sXY[k] = make_ulonglong2(pkf(p0.x, p1.x), pkf(p0.y, p1.y));
        sZW[k] = make_ulonglong2(pkf(p0.z, p1.z), pkf(p0.w, p1.w));
    }
    __syncthreads();

    const int i = blockIdx.x * BLOCK + tid;
    if (i >= n_rays) return;

    const float ox = ro[3 * i + 0];
    const float oy = ro[3 * i + 1];
    const float oz = ro[3 * i + 2];
    const float dx = rd[3 * i + 0];
    const float dy = rd[3 * i + 1];
    const float dz = rd[3 * i + 2];

    // jnp.sum(v*v): rounded squares, left-to-right add (reference order)
    const float a   = __fadd_rn(__fadd_rn(__fmul_rn(dx, dx), __fmul_rn(dy, dy)),
                                __fmul_rn(dz, dz));
    const float ddo = __fadd_rn(__fadd_rn(__fmul_rn(dx, ox), __fmul_rn(dy, oy)),
                                __fmul_rn(dz, oz));
    const float on2 = __fadd_rn(__fadd_rn(__fmul_rn(ox, ox), __fmul_rn(oy, oy)),
                                __fmul_rn(oz, oz));
    const float n2ox = __fmul_rn(-2.0f, ox);
    const float n2oy = __fmul_rn(-2.0f, oy);
    const float n2oz = __fmul_rn(-2.0f, oz);

    // Packed broadcast constants; d-chain negated, o-chain scaled by -2
    // (both exact transforms that commute with rn at every step).
    const u64 pndx  = pkf(-dx, -dx), pndy  = pkf(-dy, -dy), pndz  = pkf(-dz, -dz);
    const u64 pn2ox = pkf(n2ox, n2ox), pn2oy = pkf(n2oy, n2oy), pn2oz = pkf(n2oz, n2oz);
    const u64 pddo = pkf(ddo, ddo);
    const u64 pon2 = pkf(on2, on2);
    const u64 pna  = pkf(-a, -a);

    float best_m = CUDART_INF_F;
    float best_t = CUDART_INF_F;
    int   best_j = 0;

    // Exact scalar resolve for sphere j (bitwise mirrors a packed lane).
    auto resolve = [&](int j) {
        const float4 s = s_ctr[j];
        const float nddc  = __fmaf_rn(-dz, s.z,
                              __fmaf_rn(-dy, s.y, __fmul_rn(-dx, s.x)));
        const float n2odc = __fmaf_rn(n2oz, s.z,
                              __fmaf_rn(n2oy, s.y, __fmul_rn(n2ox, s.x)));
        const float x = __fadd_rn(ddo, nddc);                    // b/2
        const float c = __fadd_rn(__fadd_rn(on2, n2odc), s.w);
        const float q = __fadd_rn(__fmul_rn(x, x), __fmul_rn(-a, c)); // disc/4
        if (q >= 0.0f) {
            const float sq = __fsqrt_rn(q);                      // sqrt_disc/2
            const float m1 = __fsub_rn(-x, sq);
            const float m0 = __fadd_rn(-x, sq);
            const float m  = (m1 > 0.0f) ? m1 : m0;
            if (m > 0.0f && m < best_m) {
                best_m = m;
                const float t = __fdiv_rn(m, a);                 // == num/(2a)
                if (t < best_t) { best_t = t; best_j = j; }
            }
        }
    };

    if (n_pair == MAX_PAIR) {
        // ---- branch-free main loop: build 4x32-bit pair hit masks ----
        u32 msk[4];
        #pragma unroll
        for (int w = 0; w < 4; w++) {
            u32 m = 0;
            const int kb = w << 5;
            #pragma unroll 8
            for (int t = 0; t < 32; t++) {
                const ulonglong2 A = sXY[kb + t];   // {x0,x1},{y0,y1}
                const ulonglong2 B = sZW[kb + t];   // {z0,z1},{w0,w1}
                const u64 nddc  = fma2(pndz,  B.x, fma2(pndy,  A.y, mul2(pndx,  A.x)));
                const u64 n2odc = fma2(pn2oz, B.x, fma2(pn2oy, A.y, mul2(pn2ox, A.x)));
                const u64 x2 = add2(pddo, nddc);              // b/2 per lane
                const u64 c2 = add2(add2(pon2, n2odc), B.y);
                const u64 q2 = add2(mul2(x2, x2), mul2(pna, c2));  // disc/4
                // bit = "any lane >= 0" = NOT(both sign bits). (-0.0f cannot
                // occur: rn cancellation yields +0, so sign-bit <=> q < 0.)
                const u32 nb = ~((u32)q2 & (u32)(q2 >> 32));
                m = m * 2u + (nb >> 31);            // pair kb+t -> bit (31-t)
            }
            msk[w] = m;
        }

        // ---- resolution pass: ascending k via MSB-first scan ----
        #pragma unroll
        for (int w = 0; w < 4; w++) {
            u32 m = msk[w];
            while (m) {
                const int t = __clz(m);             // smallest pair index first
                m &= ~(0x80000000u >> t);
                const int k = (w << 5) + t;
                resolve(2 * k);
                resolve(2 * k + 1);
            }
        }
    } else {
        // Generic fallback (any n_sph): exact scalar per sphere
        for (int j = 0; j < n_sph; j++) resolve(j);
    }

    const float t_hit = best_t;
    const bool  any   = isfinite(t_hit);

    const long long N = n_rays;
    out[i]     = t_hit;
    out[N + i] = any ? (float)best_j : -1.0f;

    // hit_points = o + t*d (mul then add — matches reference)
    const float hx = __fadd_rn(ox, __fmul_rn(t_hit, dx));
    const float hy = __fadd_rn(oy, __fmul_rn(t_hit, dy));
    const float hz = __fadd_rn(oz, __fmul_rn(t_hit, dz));
    out[2 * N + 3 * i + 0] = hx;
    out[2 * N + 3 * i + 1] = hy;
    out[2 * N + 3 * i + 2] = hz;

    const float4 cb = s_ctr[any ? best_j : 0];
    const float nx = __fsub_rn(hx, cb.x);
    const float ny = __fsub_rn(hy, cb.y);
    const float nz = __fsub_rn(hz, cb.z);
    const float nn = __fadd_rn(__fadd_rn(__fmul_rn(nx, nx), __fmul_rn(ny, ny)),
                               __fmul_rn(nz, nz));
    const float len = __fsqrt_rn(nn);
    out[5 * N + 3 * i + 0] = any ? __fdiv_rn(nx, len) : 0.0f;
    out[5 * N + 3 * i + 1] = any ? __fdiv_rn(ny, len) : 0.0f;
    out[5 * N + 3 * i + 2] = any ? __fdiv_rn(nz, len) : 0.0f;
}

extern "C" void kernel_launch(void* const* d_in, const int* in_sizes, int n_in,
                              void* d_out, int out_size)
{
    const float* ro = (const float*)d_in[0];   // (N,3)
    const float* rd = (const float*)d_in[1];   // (N,3)
    const float* sc = (const float*)d_in[2];   // (M,3)
    const float* sr = (const float*)d_in[3];   // (M,)

    const int n_rays = in_sizes[0] / 3;
    const int n_sph  = in_sizes[3];

    float* out = (float*)d_out;

    const int grid = (n_rays + BLOCK - 1) / BLOCK;
    raysphere_kernel<<<grid, BLOCK>>>(ro, rd, sc, sr, out, n_rays, n_sph);
}